// round 8
// baseline (speedup 1.0000x reference)
#include <cuda_runtime.h>
#include <cstdint>

#define BB 8
#define LL 2048
#define DD 64
#define TQ 64
#define TK 64

// index lists for mask compaction (device globals: allocation-free scratch)
__device__ int g_qlist[BB][LL];
__device__ int g_klist[BB][LL];
__device__ int g_qcnt[BB];
__device__ int g_kcnt[BB];

// ---------------------------------------------------------------------------
// Kernel 1: deterministic per-batch compaction of valid q/k indices.
// One CTA per batch; 256 threads x 8 contiguous elements; sequential scan by
// thread 0 keeps order (and therefore fp summation order) deterministic.
// ---------------------------------------------------------------------------
__global__ void compact_kernel(const int* __restrict__ qm, const int* __restrict__ km) {
    int b = blockIdx.x;
    int tid = threadIdx.x;
    __shared__ int cnt[256];

    // ---- q mask ----
    {
        const int* m = qm + (size_t)b * LL;
        int base = tid * 8;
        int c = 0;
#pragma unroll
        for (int k = 0; k < 8; ++k) c += (m[base + k] != 0);
        cnt[tid] = c;
        __syncthreads();
        if (tid == 0) {
            int run = 0;
            for (int t = 0; t < 256; ++t) { int v = cnt[t]; cnt[t] = run; run += v; }
            g_qcnt[b] = run;
        }
        __syncthreads();
        int pos = cnt[tid];
#pragma unroll
        for (int k = 0; k < 8; ++k)
            if (m[base + k] != 0) g_qlist[b][pos++] = base + k;
        __syncthreads();
    }
    // ---- k mask ----
    {
        const int* m = km + (size_t)b * LL;
        int base = tid * 8;
        int c = 0;
#pragma unroll
        for (int k = 0; k < 8; ++k) c += (m[base + k] != 0);
        cnt[tid] = c;
        __syncthreads();
        if (tid == 0) {
            int run = 0;
            for (int t = 0; t < 256; ++t) { int v = cnt[t]; cnt[t] = run; run += v; }
            g_kcnt[b] = run;
        }
        __syncthreads();
        int pos = cnt[tid];
#pragma unroll
        for (int k = 0; k < 8; ++k)
            if (m[base + k] != 0) g_klist[b][pos++] = base + k;
    }
}

// ---------------------------------------------------------------------------
// Kernel 2: fused attention over compacted indices.
// CTA = 64 q rows of one batch; loop over 64-row k tiles.
// 256 threads as 16x16, 4x4 micro-tiles for both GEMMs.
// Smem tiles are [64][64] fp32 with XOR swizzle in float4 groups:
//   element (row, 4g..4g+3) lives at row*64 + ((g ^ row) & 15)*4
// -> all LDS.128/STS.128 are bank-conflict-free, no transposes needed.
// ---------------------------------------------------------------------------
__device__ __forceinline__ int swz(int row, int g) {
    return row * 64 + (((g ^ row) & 15) << 2);
}

extern __shared__ float smem[];

__global__ void __launch_bounds__(256, 1)
attn_kernel(const float* __restrict__ Q, const float* __restrict__ K,
            const float* __restrict__ V, float* __restrict__ out) {
    int b  = blockIdx.y;
    int nq = g_qcnt[b];
    int nk = g_kcnt[b];
    int q0 = blockIdx.x * TQ;
    if (q0 >= nq) return;   // early exit before any barrier

    float* Qs = smem;            // 4096 floats
    float* Ks = smem + 4096;     // 4096
    float* Vs = smem + 8192;     // 4096
    float* Ps = smem + 12288;    // 4096

    int tid = threadIdx.x;
    int tx = tid & 15;           // k / d micro-tile column group
    int ty = tid >> 4;           // q micro-tile row group

    // ---- load Q tile (gathered by index, pre-scaled by 1/sqrt(D)=0.125) ----
    {
        int g = tid & 15;
        int r = tid >> 4;
#pragma unroll
        for (int pass = 0; pass < 4; ++pass) {
            int row = r + pass * 16;
            int qi = q0 + row;
            float4 v = make_float4(0.f, 0.f, 0.f, 0.f);
            if (qi < nq) {
                int src = g_qlist[b][qi];
                v = *(const float4*)&Q[((size_t)b * LL + src) * DD + g * 4];
                v.x *= 0.125f; v.y *= 0.125f; v.z *= 0.125f; v.w *= 0.125f;
            }
            *(float4*)&Qs[swz(row, g)] = v;
        }
    }
    __syncthreads();

    float acc[4][4];   // O accumulator: q rows ty*4+i, d cols tx*4+j
    float rs[4];       // partial row sums over this thread's k columns
#pragma unroll
    for (int i = 0; i < 4; ++i) {
        rs[i] = 0.f;
#pragma unroll
        for (int j = 0; j < 4; ++j) acc[i][j] = 0.f;
    }

    int ntiles = (nk + TK - 1) / TK;
    for (int t = 0; t < ntiles; ++t) {
        int k0 = t * TK;

        // ---- load K and V tiles (gathered) ----
        {
            int g = tid & 15;
            int r = tid >> 4;
#pragma unroll
            for (int pass = 0; pass < 4; ++pass) {
                int row = r + pass * 16;
                int ki = k0 + row;
                float4 kv = make_float4(0.f, 0.f, 0.f, 0.f);
                float4 vv = make_float4(0.f, 0.f, 0.f, 0.f);
                if (ki < nk) {
                    int src = g_klist[b][ki];
                    const float* kp = &K[((size_t)b * LL + src) * DD + g * 4];
                    const float* vp = &V[((size_t)b * LL + src) * DD + g * 4];
                    kv = *(const float4*)kp;
                    vv = *(const float4*)vp;
                }
                *(float4*)&Ks[swz(row, g)] = kv;
                *(float4*)&Vs[swz(row, g)] = vv;
            }
        }
        __syncthreads();

        // ---- phase A: S = Qs @ Ks^T (4x4 micro-tile) ----
        float s[4][4];
#pragma unroll
        for (int i = 0; i < 4; ++i)
#pragma unroll
            for (int j = 0; j < 4; ++j) s[i][j] = 0.f;

#pragma unroll
        for (int dg = 0; dg < 16; ++dg) {
            float4 qv[4], kv[4];
#pragma unroll
            for (int i = 0; i < 4; ++i) qv[i] = *(float4*)&Qs[swz(ty * 4 + i, dg)];
#pragma unroll
            for (int j = 0; j < 4; ++j) kv[j] = *(float4*)&Ks[swz(tx * 4 + j, dg)];
#pragma unroll
            for (int i = 0; i < 4; ++i)
#pragma unroll
                for (int j = 0; j < 4; ++j)
                    s[i][j] += qv[i].x * kv[j].x + qv[i].y * kv[j].y +
                               qv[i].z * kv[j].z + qv[i].w * kv[j].w;
        }

        // exp (all compacted k are valid; only tile-padding columns masked),
        // accumulate row sums, write P tile
#pragma unroll
        for (int i = 0; i < 4; ++i) {
            float pv[4];
#pragma unroll
            for (int j = 0; j < 4; ++j) {
                int kc = k0 + tx * 4 + j;
                float e = (kc < nk) ? __expf(s[i][j]) : 0.0f;
                pv[j] = e;
                rs[i] += e;
            }
            *(float4*)&Ps[swz(ty * 4 + i, tx)] =
                make_float4(pv[0], pv[1], pv[2], pv[3]);
        }
        __syncthreads();

        // ---- phase B: O += P @ V (4x4 micro-tile over q x d) ----
#pragma unroll
        for (int kg = 0; kg < 16; ++kg) {
            float4 p[4];
#pragma unroll
            for (int i = 0; i < 4; ++i) p[i] = *(float4*)&Ps[swz(ty * 4 + i, kg)];
            float4 v0 = *(float4*)&Vs[swz(kg * 4 + 0, tx)];
            float4 v1 = *(float4*)&Vs[swz(kg * 4 + 1, tx)];
            float4 v2 = *(float4*)&Vs[swz(kg * 4 + 2, tx)];
            float4 v3 = *(float4*)&Vs[swz(kg * 4 + 3, tx)];
#pragma unroll
            for (int i = 0; i < 4; ++i) {
                acc[i][0] += p[i].x * v0.x + p[i].y * v1.x + p[i].z * v2.x + p[i].w * v3.x;
                acc[i][1] += p[i].x * v0.y + p[i].y * v1.y + p[i].z * v2.y + p[i].w * v3.y;
                acc[i][2] += p[i].x * v0.z + p[i].y * v1.z + p[i].z * v2.z + p[i].w * v3.z;
                acc[i][3] += p[i].x * v0.w + p[i].y * v1.w + p[i].z * v2.w + p[i].w * v3.w;
            }
        }
        __syncthreads();
    }

    // ---- reduce row sums across the 16 tx threads (deterministic order) ----
    float* RS = Ks;   // reuse: [qr][tx] partials, 64*16 floats
#pragma unroll
    for (int i = 0; i < 4; ++i)
        RS[(ty * 4 + i) * 16 + tx] = rs[i];
    __syncthreads();

    float* Rtot = Vs; // reuse: 64 floats
    if (tid < 64) {
        float tsum = 0.f;
#pragma unroll
        for (int u = 0; u < 16; ++u) tsum += RS[tid * 16 + u];
        Rtot[tid] = fmaxf(tsum, 1.0f);
    }
    __syncthreads();

    // ---- scale & scatter output rows back to original q positions ----
#pragma unroll
    for (int i = 0; i < 4; ++i) {
        int qr = ty * 4 + i;
        int qi = q0 + qr;
        if (qi < nq) {
            float inv = 1.0f / Rtot[qr];
            int src = g_qlist[b][qi];
            float4 o = make_float4(acc[i][0] * inv, acc[i][1] * inv,
                                   acc[i][2] * inv, acc[i][3] * inv);
            *(float4*)&out[((size_t)b * LL + src) * DD + tx * 4] = o;
        }
    }
}

// ---------------------------------------------------------------------------
extern "C" void kernel_launch(void* const* d_in, const int* in_sizes, int n_in,
                              void* d_out, int out_size) {
    const float* Q  = (const float*)d_in[0];
    const float* K  = (const float*)d_in[1];
    const float* V  = (const float*)d_in[2];
    const int*   qm = (const int*)d_in[3];
    const int*   km = (const int*)d_in[4];
    float* out = (float*)d_out;

    // 64 KB dynamic smem (> 48 KB default) — idempotent host-side config
    cudaFuncSetAttribute(attn_kernel,
                         cudaFuncAttributeMaxDynamicSharedMemorySize, 65536);

    // zero-fill output: invalid q rows stay exactly 0
    cudaMemsetAsync(out, 0, (size_t)out_size * sizeof(float));

    compact_kernel<<<BB, 256>>>(qm, km);

    dim3 grid(LL / TQ, BB);   // 32 x 8; ~half exit immediately (q compaction)
    attn_kernel<<<grid, 256, 65536>>>(Q, K, V, out);
}

// round 9
// speedup vs baseline: 1.0545x; 1.0545x over previous
#include <cuda_runtime.h>
#include <cstdint>

#define BB 8
#define LL 2048
#define DD 64
#define TQ 64
#define TK 64

// index lists for mask compaction (device globals: allocation-free scratch)
__device__ int g_qlist[BB][LL];
__device__ int g_klist[BB][LL];
__device__ int g_qcnt[BB];
__device__ int g_kcnt[BB];

// ---------------------------------------------------------------------------
// Kernel 1: deterministic per-batch compaction of valid q/k indices.
// One CTA per batch; 256 threads x 8 contiguous elements; sequential scan by
// thread 0 keeps order (and therefore fp summation order) deterministic.
// ---------------------------------------------------------------------------
__global__ void compact_kernel(const int* __restrict__ qm, const int* __restrict__ km) {
    int b = blockIdx.x;
    int tid = threadIdx.x;
    __shared__ int cnt[256];

    // ---- q mask ----
    {
        const int* m = qm + (size_t)b * LL;
        int base = tid * 8;
        int c = 0;
#pragma unroll
        for (int k = 0; k < 8; ++k) c += (m[base + k] != 0);
        cnt[tid] = c;
        __syncthreads();
        if (tid == 0) {
            int run = 0;
            for (int t = 0; t < 256; ++t) { int v = cnt[t]; cnt[t] = run; run += v; }
            g_qcnt[b] = run;
        }
        __syncthreads();
        int pos = cnt[tid];
#pragma unroll
        for (int k = 0; k < 8; ++k)
            if (m[base + k] != 0) g_qlist[b][pos++] = base + k;
        __syncthreads();
    }
    // ---- k mask ----
    {
        const int* m = km + (size_t)b * LL;
        int base = tid * 8;
        int c = 0;
#pragma unroll
        for (int k = 0; k < 8; ++k) c += (m[base + k] != 0);
        cnt[tid] = c;
        __syncthreads();
        if (tid == 0) {
            int run = 0;
            for (int t = 0; t < 256; ++t) { int v = cnt[t]; cnt[t] = run; run += v; }
            g_kcnt[b] = run;
        }
        __syncthreads();
        int pos = cnt[tid];
#pragma unroll
        for (int k = 0; k < 8; ++k)
            if (m[base + k] != 0) g_klist[b][pos++] = base + k;
    }
}

// ---------------------------------------------------------------------------
// Kernel 2: fused attention over compacted indices.
// CTA = 64 q rows of one batch; loop over 64-row k tiles.
// 256 threads as 16x16, 4x4 micro-tiles for both GEMMs.
// Smem tiles are [64][64] fp32 with XOR swizzle in float4 groups:
//   element (row, 4g..4g+3) lives at row*64 + ((g ^ row) & 15)*4
// -> all LDS.128/STS.128 are bank-conflict-free, no transposes needed.
// ---------------------------------------------------------------------------
__device__ __forceinline__ int swz(int row, int g) {
    return row * 64 + (((g ^ row) & 15) << 2);
}

extern __shared__ float smem[];

__global__ void __launch_bounds__(256, 1)
attn_kernel(const float* __restrict__ Q, const float* __restrict__ K,
            const float* __restrict__ V, float* __restrict__ out) {
    int b  = blockIdx.y;
    int nq = g_qcnt[b];
    int nk = g_kcnt[b];
    int q0 = blockIdx.x * TQ;
    if (q0 >= nq) return;   // early exit before any barrier

    float* Qs = smem;            // 4096 floats
    float* Ks = smem + 4096;     // 4096
    float* Vs = smem + 8192;     // 4096
    float* Ps = smem + 12288;    // 4096

    int tid = threadIdx.x;
    int tx = tid & 15;           // k / d micro-tile column group
    int ty = tid >> 4;           // q micro-tile row group

    // ---- load Q tile (gathered by index, pre-scaled by 1/sqrt(D)=0.125) ----
    {
        int g = tid & 15;
        int r = tid >> 4;
#pragma unroll
        for (int pass = 0; pass < 4; ++pass) {
            int row = r + pass * 16;
            int qi = q0 + row;
            float4 v = make_float4(0.f, 0.f, 0.f, 0.f);
            if (qi < nq) {
                int src = g_qlist[b][qi];
                v = *(const float4*)&Q[((size_t)b * LL + src) * DD + g * 4];
                v.x *= 0.125f; v.y *= 0.125f; v.z *= 0.125f; v.w *= 0.125f;
            }
            *(float4*)&Qs[swz(row, g)] = v;
        }
    }
    __syncthreads();

    float acc[4][4];   // O accumulator: q rows ty*4+i, d cols tx*4+j
    float rs[4];       // partial row sums over this thread's k columns
#pragma unroll
    for (int i = 0; i < 4; ++i) {
        rs[i] = 0.f;
#pragma unroll
        for (int j = 0; j < 4; ++j) acc[i][j] = 0.f;
    }

    int ntiles = (nk + TK - 1) / TK;
    for (int t = 0; t < ntiles; ++t) {
        int k0 = t * TK;

        // ---- load K and V tiles (gathered) ----
        {
            int g = tid & 15;
            int r = tid >> 4;
#pragma unroll
            for (int pass = 0; pass < 4; ++pass) {
                int row = r + pass * 16;
                int ki = k0 + row;
                float4 kv = make_float4(0.f, 0.f, 0.f, 0.f);
                float4 vv = make_float4(0.f, 0.f, 0.f, 0.f);
                if (ki < nk) {
                    int src = g_klist[b][ki];
                    const float* kp = &K[((size_t)b * LL + src) * DD + g * 4];
                    const float* vp = &V[((size_t)b * LL + src) * DD + g * 4];
                    kv = *(const float4*)kp;
                    vv = *(const float4*)vp;
                }
                *(float4*)&Ks[swz(row, g)] = kv;
                *(float4*)&Vs[swz(row, g)] = vv;
            }
        }
        __syncthreads();

        // ---- phase A: S = Qs @ Ks^T (4x4 micro-tile) ----
        float s[4][4];
#pragma unroll
        for (int i = 0; i < 4; ++i)
#pragma unroll
            for (int j = 0; j < 4; ++j) s[i][j] = 0.f;

#pragma unroll
        for (int dg = 0; dg < 16; ++dg) {
            float4 qv[4], kv[4];
#pragma unroll
            for (int i = 0; i < 4; ++i) qv[i] = *(float4*)&Qs[swz(ty * 4 + i, dg)];
#pragma unroll
            for (int j = 0; j < 4; ++j) kv[j] = *(float4*)&Ks[swz(tx * 4 + j, dg)];
#pragma unroll
            for (int i = 0; i < 4; ++i)
#pragma unroll
                for (int j = 0; j < 4; ++j)
                    s[i][j] += qv[i].x * kv[j].x + qv[i].y * kv[j].y +
                               qv[i].z * kv[j].z + qv[i].w * kv[j].w;
        }

        // exp (all compacted k are valid; only tile-padding columns masked),
        // accumulate row sums, write P tile
#pragma unroll
        for (int i = 0; i < 4; ++i) {
            float pv[4];
#pragma unroll
            for (int j = 0; j < 4; ++j) {
                int kc = k0 + tx * 4 + j;
                float e = (kc < nk) ? __expf(s[i][j]) : 0.0f;
                pv[j] = e;
                rs[i] += e;
            }
            *(float4*)&Ps[swz(ty * 4 + i, tx)] =
                make_float4(pv[0], pv[1], pv[2], pv[3]);
        }
        __syncthreads();

        // ---- phase B: O += P @ V (4x4 micro-tile over q x d) ----
#pragma unroll
        for (int kg = 0; kg < 16; ++kg) {
            float4 p[4];
#pragma unroll
            for (int i = 0; i < 4; ++i) p[i] = *(float4*)&Ps[swz(ty * 4 + i, kg)];
            float4 v0 = *(float4*)&Vs[swz(kg * 4 + 0, tx)];
            float4 v1 = *(float4*)&Vs[swz(kg * 4 + 1, tx)];
            float4 v2 = *(float4*)&Vs[swz(kg * 4 + 2, tx)];
            float4 v3 = *(float4*)&Vs[swz(kg * 4 + 3, tx)];
#pragma unroll
            for (int i = 0; i < 4; ++i) {
                acc[i][0] += p[i].x * v0.x + p[i].y * v1.x + p[i].z * v2.x + p[i].w * v3.x;
                acc[i][1] += p[i].x * v0.y + p[i].y * v1.y + p[i].z * v2.y + p[i].w * v3.y;
                acc[i][2] += p[i].x * v0.z + p[i].y * v1.z + p[i].z * v2.z + p[i].w * v3.z;
                acc[i][3] += p[i].x * v0.w + p[i].y * v1.w + p[i].z * v2.w + p[i].w * v3.w;
            }
        }
        __syncthreads();
    }

    // ---- reduce row sums across the 16 tx threads (deterministic order) ----
    float* RS = Ks;   // reuse: [qr][tx] partials, 64*16 floats
#pragma unroll
    for (int i = 0; i < 4; ++i)
        RS[(ty * 4 + i) * 16 + tx] = rs[i];
    __syncthreads();

    float* Rtot = Vs; // reuse: 64 floats
    if (tid < 64) {
        float tsum = 0.f;
#pragma unroll
        for (int u = 0; u < 16; ++u) tsum += RS[tid * 16 + u];
        Rtot[tid] = fmaxf(tsum, 1.0f);
    }
    __syncthreads();

    // ---- scale & scatter output rows back to original q positions ----
#pragma unroll
    for (int i = 0; i < 4; ++i) {
        int qr = ty * 4 + i;
        int qi = q0 + qr;
        if (qi < nq) {
            float inv = 1.0f / Rtot[qr];
            int src = g_qlist[b][qi];
            float4 o = make_float4(acc[i][0] * inv, acc[i][1] * inv,
                                   acc[i][2] * inv, acc[i][3] * inv);
            *(float4*)&out[((size_t)b * LL + src) * DD + tx * 4] = o;
        }
    }
}

// ---------------------------------------------------------------------------
extern "C" void kernel_launch(void* const* d_in, const int* in_sizes, int n_in,
                              void* d_out, int out_size) {
    const float* Q  = (const float*)d_in[0];
    const float* K  = (const float*)d_in[1];
    const float* V  = (const float*)d_in[2];
    const int*   qm = (const int*)d_in[3];
    const int*   km = (const int*)d_in[4];
    float* out = (float*)d_out;

    // 64 KB dynamic smem (> 48 KB default) — idempotent host-side config
    cudaFuncSetAttribute(attn_kernel,
                         cudaFuncAttributeMaxDynamicSharedMemorySize, 65536);

    // zero-fill output: invalid q rows stay exactly 0
    cudaMemsetAsync(out, 0, (size_t)out_size * sizeof(float));

    compact_kernel<<<BB, 256>>>(qm, km);

    dim3 grid(LL / TQ, BB);   // 32 x 8; ~half exit immediately (q compaction)
    attn_kernel<<<grid, 256, 65536>>>(Q, K, V, out);
}